// round 13
// baseline (speedup 1.0000x reference)
#include <cuda_runtime.h>
#include <cuda_bf16.h>

#define DIM   128
#define ROWV  32              // float4 per row
#define NTYP_MAX 4096
#define FUSED_GRID 592        // 4 CTAs/SM * 148 SMs -> all resident (barrier-safe)

// Precomputed group-sum table: S[j] = sum_{k=0..3} out[lcom[(j+k)%n_typ]]
__device__ float4 g_S[NTYP_MAX * ROWV];

// Monotonic barrier counter — NEVER reset -> graph-replay safe. Each barrier
// waits for the next multiple of gridDim.x, so it supports multiple barriers.
__device__ unsigned g_bar;

__device__ __forceinline__ void grid_barrier()
{
    __syncthreads();
    if (threadIdx.x == 0) {
        __threadfence();                                   // release
        unsigned t = atomicAdd(&g_bar, 1u) + 1u;
        unsigned target = ((t + gridDim.x - 1u) / gridDim.x) * gridDim.x;
        while (*(volatile unsigned*)&g_bar < target) { }
        __threadfence();                                   // acquire
    }
    __syncthreads();
}

// ---------------------------------------------------------------------------
// MEGA-KERNEL: phase 1 = sub2 | barrier | phase 2 = build_S | barrier |
// phase 3 = sub3 (2 entities per warp, grid-stride). One launch total.
// All post-barrier reads of data written in this launch use __ldcg (L2).
// ---------------------------------------------------------------------------
__global__ __launch_bounds__(256, 4)
void fused_all(const float4* __restrict__ emb4,
               const int4*   __restrict__ s2row4,   // sub2_row as int4
               const int*    __restrict__ lspec,
               const int*    __restrict__ rcom,
               const int*    __restrict__ lcom,
               const int4*   __restrict__ edges4,   // sub3_row as int4
               const int*    __restrict__ rspec,
               float4*       __restrict__ out4,
               float addc2, int n_typ, int n_ent,
               float add3, float inv_sum)
{
    __shared__ float4 part[8][ROWV];

    const int lane = threadIdx.x & 31;
    const int g    = threadIdx.x >> 5;     // warp id in block (0..7)

    // ================= phase 1: sub2 =================
    for (int c = blockIdx.x; c < n_typ; c += gridDim.x) {
        const int4 ea = __ldg(&s2row4[c * 16 + g * 2]);
        const int4 eb = __ldg(&s2row4[c * 16 + g * 2 + 1]);

        const int s0 = __ldg(&lspec[ea.x]);
        const int s1 = __ldg(&lspec[ea.y]);
        const int s2 = __ldg(&lspec[ea.z]);
        const int s3 = __ldg(&lspec[ea.w]);
        const int s4 = __ldg(&lspec[eb.x]);
        const int s5 = __ldg(&lspec[eb.y]);
        const int s6 = __ldg(&lspec[eb.z]);
        const int s7 = __ldg(&lspec[eb.w]);

        float4 v0 = __ldcs(&emb4[s0 * ROWV + lane]);
        float4 v1 = __ldcs(&emb4[s1 * ROWV + lane]);
        float4 v2 = __ldcs(&emb4[s2 * ROWV + lane]);
        float4 v3 = __ldcs(&emb4[s3 * ROWV + lane]);
        float4 v4 = __ldcs(&emb4[s4 * ROWV + lane]);
        float4 v5 = __ldcs(&emb4[s5 * ROWV + lane]);
        float4 v6 = __ldcs(&emb4[s6 * ROWV + lane]);
        float4 v7 = __ldcs(&emb4[s7 * ROWV + lane]);

        float4 a;
        a.x = ((v0.x + v1.x) + (v2.x + v3.x)) + ((v4.x + v5.x) + (v6.x + v7.x));
        a.y = ((v0.y + v1.y) + (v2.y + v3.y)) + ((v4.y + v5.y) + (v6.y + v7.y));
        a.z = ((v0.z + v1.z) + (v2.z + v3.z)) + ((v4.z + v5.z) + (v6.z + v7.z));
        a.w = ((v0.w + v1.w) + (v2.w + v3.w)) + ((v4.w + v5.w) + (v6.w + v7.w));
        part[g][lane] = a;
        __syncthreads();

        if (g == 0) {
            const int tgt = __ldg(&rcom[c]);
            float4 p0 = part[0][lane], p1 = part[1][lane];
            float4 p2 = part[2][lane], p3 = part[3][lane];
            float4 p4 = part[4][lane], p5 = part[5][lane];
            float4 p6 = part[6][lane], p7 = part[7][lane];
            float4 base = __ldg(&emb4[tgt * ROWV + lane]);
            float4 r;
            r.x = base.x + ((p0.x + p1.x) + (p2.x + p3.x))
                         + ((p4.x + p5.x) + (p6.x + p7.x)) + addc2;
            r.y = base.y + ((p0.y + p1.y) + (p2.y + p3.y))
                         + ((p4.y + p5.y) + (p6.y + p7.y)) + addc2;
            r.z = base.z + ((p0.z + p1.z) + (p2.z + p3.z))
                         + ((p4.z + p5.z) + (p6.z + p7.z)) + addc2;
            r.w = base.w + ((p0.w + p1.w) + (p2.w + p3.w))
                         + ((p4.w + p5.w) + (p6.w + p7.w)) + addc2;
            out4[tgt * ROWV + lane] = r;
        }
        __syncthreads();
    }

    grid_barrier();

    // ================= phase 2: build S =================
    {
        const int total  = n_typ * ROWV;
        const int stride = gridDim.x * blockDim.x;
        for (int i = blockIdx.x * blockDim.x + threadIdx.x; i < total; i += stride) {
            const int j  = i >> 5;
            const int ln = i & 31;
            int j1 = j + 1; if (j1 >= n_typ) j1 -= n_typ;
            int j2 = j + 2; if (j2 >= n_typ) j2 -= n_typ;
            int j3 = j + 3; if (j3 >= n_typ) j3 -= n_typ;
            const int t0 = __ldg(&lcom[j]);
            const int t1 = __ldg(&lcom[j1]);
            const int t2 = __ldg(&lcom[j2]);
            const int t3 = __ldg(&lcom[j3]);
            float4 v0 = __ldcg(&out4[t0 * ROWV + ln]);
            float4 v1 = __ldcg(&out4[t1 * ROWV + ln]);
            float4 v2 = __ldcg(&out4[t2 * ROWV + ln]);
            float4 v3 = __ldcg(&out4[t3 * ROWV + ln]);
            float4 s;
            s.x = (v0.x + v1.x) + (v2.x + v3.x);
            s.y = (v0.y + v1.y) + (v2.y + v3.y);
            s.z = (v0.z + v1.z) + (v2.z + v3.z);
            s.w = (v0.w + v1.w) + (v2.w + v3.w);
            g_S[i] = s;
        }
    }

    grid_barrier();

    // ================= phase 3: sub3 (2 entities per warp) =================
    {
        const int nwarps = gridDim.x * (blockDim.x >> 5);
        const int w      = blockIdx.x * (blockDim.x >> 5) + g;

        for (int idx = w; idx * 2 < n_ent; idx += nwarps) {
            const int base = idx * 2;
            const bool has1 = (base + 1) < n_ent;

            const int4 e0 = __ldg(&edges4[base]);
            const int4 e1 = has1 ? __ldg(&edges4[base + 1]) : e0;
            const int  r0 = __ldg(&rspec[base]);
            const int  r1 = has1 ? __ldg(&rspec[base + 1]) : r0;

            float4 iv0 = __ldcs(&emb4[r0 * ROWV + lane]);
            float4 iv1 = __ldcs(&emb4[r1 * ROWV + lane]);

            const int d01 = e0.y - e0.x, d02 = e0.z - e0.x, d03 = e0.w - e0.x;
            const bool ok0 = (d01 == 1 || d01 == 1 - n_typ)
                          && (d02 == 2 || d02 == 2 - n_typ)
                          && (d03 == 3 || d03 == 3 - n_typ);
            const int d11 = e1.y - e1.x, d12 = e1.z - e1.x, d13 = e1.w - e1.x;
            const bool ok1 = (d11 == 1 || d11 == 1 - n_typ)
                          && (d12 == 2 || d12 == 2 - n_typ)
                          && (d13 == 3 || d13 == 3 - n_typ);

            float4 a0, a1;
            if (ok0) {
                a0 = __ldcg(&g_S[e0.x * ROWV + lane]);
            } else {
                const int t0 = __ldg(&lcom[e0.x]), t1 = __ldg(&lcom[e0.y]);
                const int t2 = __ldg(&lcom[e0.z]), t3 = __ldg(&lcom[e0.w]);
                float4 g0 = __ldcg(&out4[t0 * ROWV + lane]);
                float4 g1 = __ldcg(&out4[t1 * ROWV + lane]);
                float4 g2 = __ldcg(&out4[t2 * ROWV + lane]);
                float4 g3 = __ldcg(&out4[t3 * ROWV + lane]);
                a0.x = (g0.x + g1.x) + (g2.x + g3.x);
                a0.y = (g0.y + g1.y) + (g2.y + g3.y);
                a0.z = (g0.z + g1.z) + (g2.z + g3.z);
                a0.w = (g0.w + g1.w) + (g2.w + g3.w);
            }
            if (ok1) {
                a1 = __ldcg(&g_S[e1.x * ROWV + lane]);
            } else {
                const int t0 = __ldg(&lcom[e1.x]), t1 = __ldg(&lcom[e1.y]);
                const int t2 = __ldg(&lcom[e1.z]), t3 = __ldg(&lcom[e1.w]);
                float4 g0 = __ldcg(&out4[t0 * ROWV + lane]);
                float4 g1 = __ldcg(&out4[t1 * ROWV + lane]);
                float4 g2 = __ldcg(&out4[t2 * ROWV + lane]);
                float4 g3 = __ldcg(&out4[t3 * ROWV + lane]);
                a1.x = (g0.x + g1.x) + (g2.x + g3.x);
                a1.y = (g0.y + g1.y) + (g2.y + g3.y);
                a1.z = (g0.z + g1.z) + (g2.z + g3.z);
                a1.w = (g0.w + g1.w) + (g2.w + g3.w);
            }

            float4 w0;
            w0.x = iv0.x * (1.0f - (a0.x + add3) * inv_sum);
            w0.y = iv0.y * (1.0f - (a0.y + add3) * inv_sum);
            w0.z = iv0.z * (1.0f - (a0.z + add3) * inv_sum);
            w0.w = iv0.w * (1.0f - (a0.w + add3) * inv_sum);
            __stcs(&out4[r0 * ROWV + lane], w0);

            if (has1) {
                float4 w1;
                w1.x = iv1.x * (1.0f - (a1.x + add3) * inv_sum);
                w1.y = iv1.y * (1.0f - (a1.y + add3) * inv_sum);
                w1.z = iv1.z * (1.0f - (a1.z + add3) * inv_sum);
                w1.w = iv1.w * (1.0f - (a1.w + add3) * inv_sum);
                __stcs(&out4[r1 * ROWV + lane], w1);
            }
        }
    }
}

// ---------------------------------------------------------------------------
// Fallback kernels (generic shapes).
// ---------------------------------------------------------------------------
__global__ __launch_bounds__(512)
void sub2_kernel_gen(const float* __restrict__ emb,
                     const int*   __restrict__ s2row,
                     const int*   __restrict__ lspec,
                     const int*   __restrict__ rcom,
                     float*       __restrict__ out,
                     float addc, int deg2)
{
    __shared__ float part[4][DIM];
    const int c = blockIdx.x;
    const int d = threadIdx.x & (DIM - 1);
    const int g = threadIdx.x >> 7;
    const int* __restrict__ e = s2row + (size_t)c * deg2;
    const int chunk = deg2 >> 2;
    const int j0 = g * chunk;
    const int j1 = (g == 3) ? deg2 : j0 + chunk;
    float acc = 0.0f;
    #pragma unroll 8
    for (int j = j0; j < j1; ++j) {
        int src = __ldg(&lspec[__ldg(&e[j])]);
        acc += __ldcs(&emb[(size_t)src * DIM + d]);
    }
    part[g][d] = acc;
    __syncthreads();
    if (g == 0) {
        const int tgt = rcom[c];
        float v = __ldg(&emb[(size_t)tgt * DIM + d])
                + part[0][d] + part[1][d] + part[2][d] + part[3][d] + addc;
        out[(size_t)tgt * DIM + d] = v;
    }
}

__global__ __launch_bounds__(256)
void sub3_kernel_gen(const float* __restrict__ emb,
                     const int*   __restrict__ s3row,
                     const int*   __restrict__ lcom,
                     const int*   __restrict__ rspec,
                     float*       __restrict__ out,
                     int n_ent, float n_typ_f, int deg3)
{
    const int warp = threadIdx.x >> 5;
    const int lane = threadIdx.x & 31;
    const int n = blockIdx.x * (blockDim.x >> 5) + warp;
    if (n >= n_ent) return;

    const float4* __restrict__ out4 = (const float4*)out;
    const int* __restrict__ e = s3row + (size_t)n * deg3;

    float4 acc = make_float4(0.f, 0.f, 0.f, 0.f);
    for (int j = 0; j < deg3; ++j) {
        int t = __ldg(&lcom[__ldg(&e[j])]);
        float4 v = __ldg(&out4[(size_t)t * ROWV + lane]);
        acc.x += v.x; acc.y += v.y; acc.z += v.z; acc.w += v.w;
    }
    const float add     = n_typ_f - (float)deg3;
    const float inv_sum = 1.0f / (1.0f + (float)deg3);
    const int   tgt     = rspec[n];
    float4 iv = __ldcs(&((const float4*)emb)[(size_t)tgt * ROWV + lane]);
    float4 r;
    r.x = iv.x * (1.0f - (acc.x + add) * inv_sum);
    r.y = iv.y * (1.0f - (acc.y + add) * inv_sum);
    r.z = iv.z * (1.0f - (acc.z + add) * inv_sum);
    r.w = iv.w * (1.0f - (acc.w + add) * inv_sum);
    __stcs(&((float4*)out)[(size_t)tgt * ROWV + lane], r);
}

// ---------------------------------------------------------------------------
// Launch. Inputs (metadata order):
//  0 all_node_embedding f32 | 1 sub2_row | 2 sub2_col | 3 sub3_row | 4 sub3_col
//  5 left_specific | 6 right_common | 7 left_common | 8 right_specific
// ---------------------------------------------------------------------------
extern "C" void kernel_launch(void* const* d_in, const int* in_sizes, int n_in,
                              void* d_out, int out_size)
{
    const float* emb   = (const float*)d_in[0];
    const int*   s2row = (const int*)  d_in[1];
    const int*   s3row = (const int*)  d_in[3];
    const int*   lspec = (const int*)  d_in[5];
    const int*   rcom  = (const int*)  d_in[6];
    const int*   lcom  = (const int*)  d_in[7];
    const int*   rspec = (const int*)  d_in[8];
    float*       out   = (float*)d_out;

    const int n_ent = in_sizes[5];
    const int n_typ = in_sizes[6];
    const int deg2  = in_sizes[1] / n_typ;
    const int deg3  = in_sizes[3] / in_sizes[8];

    if (deg2 == 64 && deg3 == 4 && n_typ <= NTYP_MAX) {
        // ONE persistent kernel: sub2 | barrier | build_S | barrier | sub3
        fused_all<<<FUSED_GRID, 256>>>(
            (const float4*)emb, (const int4*)s2row, lspec, rcom, lcom,
            (const int4*)s3row, rspec, (float4*)out,
            (float)n_ent - (float)deg2, n_typ, n_ent,
            (float)n_typ - 4.0f, 1.0f / 5.0f);
    } else {
        // generic fallback path
        sub2_kernel_gen<<<n_typ, 512>>>(emb, s2row, lspec, rcom, out,
                                        (float)n_ent - (float)deg2, deg2);
        const int warps_per_block = 8;
        const int blocks = (n_ent + warps_per_block - 1) / warps_per_block;
        sub3_kernel_gen<<<blocks, warps_per_block * 32>>>(
            emb, s3row, lcom, rspec, out, n_ent, (float)n_typ, deg3);
    }
}

// round 14
// speedup vs baseline: 1.0697x; 1.0697x over previous
#include <cuda_runtime.h>
#include <cuda_bf16.h>

#define DIM   128
#define ROWV  32              // float4 per row
#define NTYP_MAX 4096
#define FUSED_GRID 592        // 4 CTAs/SM * 148 SMs -> all resident (barrier-safe)

// Precomputed group-sum table: S[j] = sum_{k=0..3} out[lcom[(j+k)%n_typ]]
__device__ float4 g_S[NTYP_MAX * ROWV];

// Monotonic barrier counter — NEVER reset -> graph-replay safe.
__device__ unsigned g_bar;

// Pattern flag: 0 = edges affine-consecutive AND rspec identity (fast path OK).
// Zeroed each launch by cudaMemsetAsync in kernel_launch.
__device__ int g_bad;

// ---------------------------------------------------------------------------
// Fused front kernel: phase 1 = sub2 | grid barrier | phase 2 = build_S +
// edge-pattern verification. (R10 structure + verify pass.)
// ---------------------------------------------------------------------------
__global__ __launch_bounds__(256, 4)
void sub2_buildS_fused(const float4* __restrict__ emb4,
                       const int4*   __restrict__ s2row4,
                       const int*    __restrict__ lspec,
                       const int*    __restrict__ rcom,
                       const int*    __restrict__ lcom,
                       const int4*   __restrict__ edges4,
                       const int*    __restrict__ rspec,
                       float4*       __restrict__ out4,
                       float addc, int n_typ, int n_ent)
{
    __shared__ float4 part[8][ROWV];

    const int lane = threadIdx.x & 31;
    const int g    = threadIdx.x >> 5;

    // ================= phase 1: sub2 =================
    for (int c = blockIdx.x; c < n_typ; c += gridDim.x) {
        const int4 ea = __ldg(&s2row4[c * 16 + g * 2]);
        const int4 eb = __ldg(&s2row4[c * 16 + g * 2 + 1]);

        const int s0 = __ldg(&lspec[ea.x]);
        const int s1 = __ldg(&lspec[ea.y]);
        const int s2 = __ldg(&lspec[ea.z]);
        const int s3 = __ldg(&lspec[ea.w]);
        const int s4 = __ldg(&lspec[eb.x]);
        const int s5 = __ldg(&lspec[eb.y]);
        const int s6 = __ldg(&lspec[eb.z]);
        const int s7 = __ldg(&lspec[eb.w]);

        float4 v0 = __ldcs(&emb4[s0 * ROWV + lane]);
        float4 v1 = __ldcs(&emb4[s1 * ROWV + lane]);
        float4 v2 = __ldcs(&emb4[s2 * ROWV + lane]);
        float4 v3 = __ldcs(&emb4[s3 * ROWV + lane]);
        float4 v4 = __ldcs(&emb4[s4 * ROWV + lane]);
        float4 v5 = __ldcs(&emb4[s5 * ROWV + lane]);
        float4 v6 = __ldcs(&emb4[s6 * ROWV + lane]);
        float4 v7 = __ldcs(&emb4[s7 * ROWV + lane]);

        float4 a;
        a.x = ((v0.x + v1.x) + (v2.x + v3.x)) + ((v4.x + v5.x) + (v6.x + v7.x));
        a.y = ((v0.y + v1.y) + (v2.y + v3.y)) + ((v4.y + v5.y) + (v6.y + v7.y));
        a.z = ((v0.z + v1.z) + (v2.z + v3.z)) + ((v4.z + v5.z) + (v6.z + v7.z));
        a.w = ((v0.w + v1.w) + (v2.w + v3.w)) + ((v4.w + v5.w) + (v6.w + v7.w));
        part[g][lane] = a;
        __syncthreads();

        if (g == 0) {
            const int tgt = __ldg(&rcom[c]);
            float4 p0 = part[0][lane], p1 = part[1][lane];
            float4 p2 = part[2][lane], p3 = part[3][lane];
            float4 p4 = part[4][lane], p5 = part[5][lane];
            float4 p6 = part[6][lane], p7 = part[7][lane];
            float4 base = __ldg(&emb4[tgt * ROWV + lane]);
            float4 r;
            r.x = base.x + ((p0.x + p1.x) + (p2.x + p3.x))
                         + ((p4.x + p5.x) + (p6.x + p7.x)) + addc;
            r.y = base.y + ((p0.y + p1.y) + (p2.y + p3.y))
                         + ((p4.y + p5.y) + (p6.y + p7.y)) + addc;
            r.z = base.z + ((p0.z + p1.z) + (p2.z + p3.z))
                         + ((p4.z + p5.z) + (p6.z + p7.z)) + addc;
            r.w = base.w + ((p0.w + p1.w) + (p2.w + p3.w))
                         + ((p4.w + p5.w) + (p6.w + p7.w)) + addc;
            out4[tgt * ROWV + lane] = r;
        }
        __syncthreads();
    }

    // grid barrier (all CTAs resident via __launch_bounds__(256,4))
    __syncthreads();
    if (threadIdx.x == 0) {
        __threadfence();
        unsigned t = atomicAdd(&g_bar, 1u) + 1u;
        unsigned target = ((t + gridDim.x - 1u) / gridDim.x) * gridDim.x;
        while (*(volatile unsigned*)&g_bar < target) { }
        __threadfence();
    }
    __syncthreads();

    // ================= phase 2a: build S (reads via __ldcg) =================
    {
        const int total  = n_typ * ROWV;
        const int stride = gridDim.x * blockDim.x;
        for (int i = blockIdx.x * blockDim.x + threadIdx.x; i < total; i += stride) {
            const int j  = i >> 5;
            const int ln = i & 31;
            int j1 = j + 1; if (j1 >= n_typ) j1 -= n_typ;
            int j2 = j + 2; if (j2 >= n_typ) j2 -= n_typ;
            int j3 = j + 3; if (j3 >= n_typ) j3 -= n_typ;
            const int t0 = __ldg(&lcom[j]);
            const int t1 = __ldg(&lcom[j1]);
            const int t2 = __ldg(&lcom[j2]);
            const int t3 = __ldg(&lcom[j3]);
            float4 v0 = __ldcg(&out4[t0 * ROWV + ln]);
            float4 v1 = __ldcg(&out4[t1 * ROWV + ln]);
            float4 v2 = __ldcg(&out4[t2 * ROWV + ln]);
            float4 v3 = __ldcg(&out4[t3 * ROWV + ln]);
            float4 s;
            s.x = (v0.x + v1.x) + (v2.x + v3.x);
            s.y = (v0.y + v1.y) + (v2.y + v3.y);
            s.z = (v0.z + v1.z) + (v2.z + v3.z);
            s.w = (v0.w + v1.w) + (v2.w + v3.w);
            g_S[i] = s;
        }
    }

    // ================= phase 2b: verify affine edge pattern ===============
    // Pattern: edges4[n] == (x, x+1, x+2, x+3) mod n_typ with x = (b+a*n)%n_typ
    // and rspec[n] == n. Any mismatch -> g_bad = 1 (sub3 takes generic path).
    {
        if (n_ent < 2) {
            if (blockIdx.x == 0 && threadIdx.x == 0) g_bad = 1;
        } else {
            const int4 h0 = __ldg(&edges4[0]);
            const int4 h1 = __ldg(&edges4[1]);
            const int b = h0.x;
            int a = h1.x - b; if (a < 0) a += n_typ;
            bool bad = false;
            const int stride = gridDim.x * blockDim.x;
            for (int n = blockIdx.x * blockDim.x + threadIdx.x; n < n_ent; n += stride) {
                const int4 e = __ldcs(&edges4[n]);
                const int r = __ldcs(&rspec[n]);
                int x = (int)(((long long)a * n + b) % n_typ);
                int y = x + 1; if (y >= n_typ) y -= n_typ;
                int z = x + 2; if (z >= n_typ) z -= n_typ;
                int w = x + 3; if (w >= n_typ) w -= n_typ;
                if (e.x != x || e.y != y || e.z != z || e.w != w || r != n)
                    bad = true;
            }
            if (__syncthreads_or(bad ? 1 : 0)) {
                if (threadIdx.x == 0) atomicExch(&g_bad, 1);
            }
        }
    }
}

// ---------------------------------------------------------------------------
// sub3 (deg3==4): one warp per TWO entity rows.
// Fast path (g_bad==0): S index computed ARITHMETICALLY — zero edge/rspec
// loads; chain = ALU idx -> L2 S-gather (parallel with DRAM iv load) -> store.
// Fallback (g_bad!=0): exact R10 body (full generality).
// ---------------------------------------------------------------------------
__global__ __launch_bounds__(256)
void sub3_kernel(const float4* __restrict__ emb4,
                 const int4*   __restrict__ edges4,
                 const int*    __restrict__ lcom,
                 const int*    __restrict__ rspec,
                 float4*       __restrict__ out4,
                 int n_ent, int n_typ, float add, float inv_sum)
{
    const int warp = threadIdx.x >> 5;
    const int lane = threadIdx.x & 31;
    const int base = (blockIdx.x * (blockDim.x >> 5) + warp) * 2;
    if (base >= n_ent) return;
    const bool has1 = (base + 1) < n_ent;

    if (g_bad == 0) {
        // ---------- fast path: no edge/rspec loads ----------
        const int4 h0 = __ldg(&edges4[0]);
        const int4 h1 = __ldg(&edges4[1]);
        const int b = h0.x;
        int a = h1.x - b; if (a < 0) a += n_typ;

        const int ex0 = (int)(((long long)a * base + b) % n_typ);
        int ex1 = ex0 + a; if (ex1 >= n_typ) ex1 -= n_typ;

        // independent loads: 2 DRAM-streaming iv + 2 L2 S-gathers
        float4 iv0 = __ldcs(&emb4[base * ROWV + lane]);
        float4 iv1 = __ldcs(&emb4[(base + 1 < n_ent ? base + 1 : base) * ROWV + lane]);
        float4 a0  = __ldcg(&g_S[ex0 * ROWV + lane]);
        float4 a1  = __ldcg(&g_S[ex1 * ROWV + lane]);

        float4 w0;
        w0.x = iv0.x * (1.0f - (a0.x + add) * inv_sum);
        w0.y = iv0.y * (1.0f - (a0.y + add) * inv_sum);
        w0.z = iv0.z * (1.0f - (a0.z + add) * inv_sum);
        w0.w = iv0.w * (1.0f - (a0.w + add) * inv_sum);
        __stcs(&out4[base * ROWV + lane], w0);

        if (has1) {
            float4 w1;
            w1.x = iv1.x * (1.0f - (a1.x + add) * inv_sum);
            w1.y = iv1.y * (1.0f - (a1.y + add) * inv_sum);
            w1.z = iv1.z * (1.0f - (a1.z + add) * inv_sum);
            w1.w = iv1.w * (1.0f - (a1.w + add) * inv_sum);
            __stcs(&out4[(base + 1) * ROWV + lane], w1);
        }
        return;
    }

    // ---------- generic fallback (R10 body) ----------
    const int4 e0 = __ldg(&edges4[base]);
    const int4 e1 = has1 ? __ldg(&edges4[base + 1]) : e0;
    const int  r0 = __ldg(&rspec[base]);
    const int  r1 = has1 ? __ldg(&rspec[base + 1]) : r0;

    float4 iv0 = __ldcs(&emb4[r0 * ROWV + lane]);
    float4 iv1 = __ldcs(&emb4[r1 * ROWV + lane]);

    const int d01 = e0.y - e0.x, d02 = e0.z - e0.x, d03 = e0.w - e0.x;
    const bool ok0 = (d01 == 1 || d01 == 1 - n_typ)
                  && (d02 == 2 || d02 == 2 - n_typ)
                  && (d03 == 3 || d03 == 3 - n_typ);
    const int d11 = e1.y - e1.x, d12 = e1.z - e1.x, d13 = e1.w - e1.x;
    const bool ok1 = (d11 == 1 || d11 == 1 - n_typ)
                  && (d12 == 2 || d12 == 2 - n_typ)
                  && (d13 == 3 || d13 == 3 - n_typ);

    float4 a0, a1;
    if (ok0) {
        a0 = __ldcg(&g_S[e0.x * ROWV + lane]);
    } else {
        const int t0 = __ldg(&lcom[e0.x]), t1 = __ldg(&lcom[e0.y]);
        const int t2 = __ldg(&lcom[e0.z]), t3 = __ldg(&lcom[e0.w]);
        float4 g0 = __ldcg(&out4[t0 * ROWV + lane]);
        float4 g1 = __ldcg(&out4[t1 * ROWV + lane]);
        float4 g2 = __ldcg(&out4[t2 * ROWV + lane]);
        float4 g3 = __ldcg(&out4[t3 * ROWV + lane]);
        a0.x = (g0.x + g1.x) + (g2.x + g3.x);
        a0.y = (g0.y + g1.y) + (g2.y + g3.y);
        a0.z = (g0.z + g1.z) + (g2.z + g3.z);
        a0.w = (g0.w + g1.w) + (g2.w + g3.w);
    }
    if (ok1) {
        a1 = __ldcg(&g_S[e1.x * ROWV + lane]);
    } else {
        const int t0 = __ldg(&lcom[e1.x]), t1 = __ldg(&lcom[e1.y]);
        const int t2 = __ldg(&lcom[e1.z]), t3 = __ldg(&lcom[e1.w]);
        float4 g0 = __ldcg(&out4[t0 * ROWV + lane]);
        float4 g1 = __ldcg(&out4[t1 * ROWV + lane]);
        float4 g2 = __ldcg(&out4[t2 * ROWV + lane]);
        float4 g3 = __ldcg(&out4[t3 * ROWV + lane]);
        a1.x = (g0.x + g1.x) + (g2.x + g3.x);
        a1.y = (g0.y + g1.y) + (g2.y + g3.y);
        a1.z = (g0.z + g1.z) + (g2.z + g3.z);
        a1.w = (g0.w + g1.w) + (g2.w + g3.w);
    }

    float4 w0;
    w0.x = iv0.x * (1.0f - (a0.x + add) * inv_sum);
    w0.y = iv0.y * (1.0f - (a0.y + add) * inv_sum);
    w0.z = iv0.z * (1.0f - (a0.z + add) * inv_sum);
    w0.w = iv0.w * (1.0f - (a0.w + add) * inv_sum);
    __stcs(&out4[r0 * ROWV + lane], w0);

    if (has1) {
        float4 w1;
        w1.x = iv1.x * (1.0f - (a1.x + add) * inv_sum);
        w1.y = iv1.y * (1.0f - (a1.y + add) * inv_sum);
        w1.z = iv1.z * (1.0f - (a1.z + add) * inv_sum);
        w1.w = iv1.w * (1.0f - (a1.w + add) * inv_sum);
        __stcs(&out4[r1 * ROWV + lane], w1);
    }
}

// ---------------------------------------------------------------------------
// Fallback kernels (generic shapes).
// ---------------------------------------------------------------------------
__global__ __launch_bounds__(512)
void sub2_kernel_gen(const float* __restrict__ emb,
                     const int*   __restrict__ s2row,
                     const int*   __restrict__ lspec,
                     const int*   __restrict__ rcom,
                     float*       __restrict__ out,
                     float addc, int deg2)
{
    __shared__ float part[4][DIM];
    const int c = blockIdx.x;
    const int d = threadIdx.x & (DIM - 1);
    const int g = threadIdx.x >> 7;
    const int* __restrict__ e = s2row + (size_t)c * deg2;
    const int chunk = deg2 >> 2;
    const int j0 = g * chunk;
    const int j1 = (g == 3) ? deg2 : j0 + chunk;
    float acc = 0.0f;
    #pragma unroll 8
    for (int j = j0; j < j1; ++j) {
        int src = __ldg(&lspec[__ldg(&e[j])]);
        acc += __ldcs(&emb[(size_t)src * DIM + d]);
    }
    part[g][d] = acc;
    __syncthreads();
    if (g == 0) {
        const int tgt = rcom[c];
        float v = __ldg(&emb[(size_t)tgt * DIM + d])
                + part[0][d] + part[1][d] + part[2][d] + part[3][d] + addc;
        out[(size_t)tgt * DIM + d] = v;
    }
}

__global__ __launch_bounds__(256)
void sub3_kernel_gen(const float* __restrict__ emb,
                     const int*   __restrict__ s3row,
                     const int*   __restrict__ lcom,
                     const int*   __restrict__ rspec,
                     float*       __restrict__ out,
                     int n_ent, float n_typ_f, int deg3)
{
    const int warp = threadIdx.x >> 5;
    const int lane = threadIdx.x & 31;
    const int n = blockIdx.x * (blockDim.x >> 5) + warp;
    if (n >= n_ent) return;

    const float4* __restrict__ out4 = (const float4*)out;
    const int* __restrict__ e = s3row + (size_t)n * deg3;

    float4 acc = make_float4(0.f, 0.f, 0.f, 0.f);
    for (int j = 0; j < deg3; ++j) {
        int t = __ldg(&lcom[__ldg(&e[j])]);
        float4 v = __ldg(&out4[(size_t)t * ROWV + lane]);
        acc.x += v.x; acc.y += v.y; acc.z += v.z; acc.w += v.w;
    }
    const float add     = n_typ_f - (float)deg3;
    const float inv_sum = 1.0f / (1.0f + (float)deg3);
    const int   tgt     = rspec[n];
    float4 iv = __ldcs(&((const float4*)emb)[(size_t)tgt * ROWV + lane]);
    float4 r;
    r.x = iv.x * (1.0f - (acc.x + add) * inv_sum);
    r.y = iv.y * (1.0f - (acc.y + add) * inv_sum);
    r.z = iv.z * (1.0f - (acc.z + add) * inv_sum);
    r.w = iv.w * (1.0f - (acc.w + add) * inv_sum);
    __stcs(&((float4*)out)[(size_t)tgt * ROWV + lane], r);
}

// ---------------------------------------------------------------------------
// Launch. Inputs (metadata order):
//  0 all_node_embedding f32 | 1 sub2_row | 2 sub2_col | 3 sub3_row | 4 sub3_col
//  5 left_specific | 6 right_common | 7 left_common | 8 right_specific
// ---------------------------------------------------------------------------
extern "C" void kernel_launch(void* const* d_in, const int* in_sizes, int n_in,
                              void* d_out, int out_size)
{
    const float* emb   = (const float*)d_in[0];
    const int*   s2row = (const int*)  d_in[1];
    const int*   s3row = (const int*)  d_in[3];
    const int*   lspec = (const int*)  d_in[5];
    const int*   rcom  = (const int*)  d_in[6];
    const int*   lcom  = (const int*)  d_in[7];
    const int*   rspec = (const int*)  d_in[8];
    float*       out   = (float*)d_out;

    const int n_ent = in_sizes[5];
    const int n_typ = in_sizes[6];
    const int deg2  = in_sizes[1] / n_typ;
    const int deg3  = in_sizes[3] / in_sizes[8];

    if (deg2 == 64 && deg3 == 4 && n_typ <= NTYP_MAX) {
        // zero the per-launch pattern flag (graph-capturable async memset)
        static void* bad_ptr = nullptr;
        if (!bad_ptr) cudaGetSymbolAddress(&bad_ptr, g_bad);
        cudaMemsetAsync(bad_ptr, 0, sizeof(int), 0);

        // fused sub2 | barrier | build_S + verify  (one launch)
        sub2_buildS_fused<<<FUSED_GRID, 256>>>(
            (const float4*)emb, (const int4*)s2row, lspec, rcom, lcom,
            (const int4*)s3row, rspec, (float4*)out,
            (float)n_ent - (float)deg2, n_typ, n_ent);

        // sub3: 2 entities per warp, arithmetic-index fast path
        const int warps_per_block = 8;
        const int ents_per_block  = warps_per_block * 2;
        const int blocks = (n_ent + ents_per_block - 1) / ents_per_block;
        sub3_kernel<<<blocks, warps_per_block * 32>>>(
            (const float4*)emb, (const int4*)s3row, lcom, rspec,
            (float4*)out, n_ent, n_typ,
            (float)n_typ - 4.0f, 1.0f / 5.0f);
    } else {
        // generic fallback path
        sub2_kernel_gen<<<n_typ, 512>>>(emb, s2row, lspec, rcom, out,
                                        (float)n_ent - (float)deg2, deg2);
        const int warps_per_block = 8;
        const int blocks = (n_ent + warps_per_block - 1) / warps_per_block;
        sub3_kernel_gen<<<blocks, warps_per_block * 32>>>(
            emb, s3row, lcom, rspec, out, n_ent, (float)n_typ, deg3);
    }
}

// round 15
// speedup vs baseline: 1.0977x; 1.0263x over previous
#include <cuda_runtime.h>
#include <cuda_bf16.h>

#define DIM   128
#define ROWV  32              // float4 per row
#define NTYP_MAX 4096
#define FUSED_GRID 592        // 4 CTAs/SM * 148 SMs -> all resident (barrier-safe)

// Precomputed group-sum table: S[j] = sum_{k=0..3} out[lcom[(j+k)%n_typ]]
__device__ float4 g_S[NTYP_MAX * ROWV];

// Monotonic barrier counter — NEVER reset -> graph-replay safe.
__device__ unsigned g_bar;

// ---------------------------------------------------------------------------
// Fused front kernel (exact R10 form): phase 1 = sub2 | grid barrier |
// phase 2 = build_S. No verification pass, no flags.
// ---------------------------------------------------------------------------
__global__ __launch_bounds__(256, 4)
void sub2_buildS_fused(const float4* __restrict__ emb4,
                       const int4*   __restrict__ s2row4,
                       const int*    __restrict__ lspec,
                       const int*    __restrict__ rcom,
                       const int*    __restrict__ lcom,
                       float4*       __restrict__ out4,
                       float addc, int n_typ)
{
    __shared__ float4 part[8][ROWV];

    const int lane = threadIdx.x & 31;
    const int g    = threadIdx.x >> 5;

    for (int c = blockIdx.x; c < n_typ; c += gridDim.x) {
        const int4 ea = __ldg(&s2row4[c * 16 + g * 2]);
        const int4 eb = __ldg(&s2row4[c * 16 + g * 2 + 1]);

        const int s0 = __ldg(&lspec[ea.x]);
        const int s1 = __ldg(&lspec[ea.y]);
        const int s2 = __ldg(&lspec[ea.z]);
        const int s3 = __ldg(&lspec[ea.w]);
        const int s4 = __ldg(&lspec[eb.x]);
        const int s5 = __ldg(&lspec[eb.y]);
        const int s6 = __ldg(&lspec[eb.z]);
        const int s7 = __ldg(&lspec[eb.w]);

        float4 v0 = __ldcs(&emb4[s0 * ROWV + lane]);
        float4 v1 = __ldcs(&emb4[s1 * ROWV + lane]);
        float4 v2 = __ldcs(&emb4[s2 * ROWV + lane]);
        float4 v3 = __ldcs(&emb4[s3 * ROWV + lane]);
        float4 v4 = __ldcs(&emb4[s4 * ROWV + lane]);
        float4 v5 = __ldcs(&emb4[s5 * ROWV + lane]);
        float4 v6 = __ldcs(&emb4[s6 * ROWV + lane]);
        float4 v7 = __ldcs(&emb4[s7 * ROWV + lane]);

        float4 a;
        a.x = ((v0.x + v1.x) + (v2.x + v3.x)) + ((v4.x + v5.x) + (v6.x + v7.x));
        a.y = ((v0.y + v1.y) + (v2.y + v3.y)) + ((v4.y + v5.y) + (v6.y + v7.y));
        a.z = ((v0.z + v1.z) + (v2.z + v3.z)) + ((v4.z + v5.z) + (v6.z + v7.z));
        a.w = ((v0.w + v1.w) + (v2.w + v3.w)) + ((v4.w + v5.w) + (v6.w + v7.w));
        part[g][lane] = a;
        __syncthreads();

        if (g == 0) {
            const int tgt = __ldg(&rcom[c]);
            float4 p0 = part[0][lane], p1 = part[1][lane];
            float4 p2 = part[2][lane], p3 = part[3][lane];
            float4 p4 = part[4][lane], p5 = part[5][lane];
            float4 p6 = part[6][lane], p7 = part[7][lane];
            float4 base = __ldg(&emb4[tgt * ROWV + lane]);
            float4 r;
            r.x = base.x + ((p0.x + p1.x) + (p2.x + p3.x))
                         + ((p4.x + p5.x) + (p6.x + p7.x)) + addc;
            r.y = base.y + ((p0.y + p1.y) + (p2.y + p3.y))
                         + ((p4.y + p5.y) + (p6.y + p7.y)) + addc;
            r.z = base.z + ((p0.z + p1.z) + (p2.z + p3.z))
                         + ((p4.z + p5.z) + (p6.z + p7.z)) + addc;
            r.w = base.w + ((p0.w + p1.w) + (p2.w + p3.w))
                         + ((p4.w + p5.w) + (p6.w + p7.w)) + addc;
            out4[tgt * ROWV + lane] = r;
        }
        __syncthreads();
    }

    // grid barrier (all CTAs resident via __launch_bounds__(256,4))
    __syncthreads();
    if (threadIdx.x == 0) {
        __threadfence();
        unsigned t = atomicAdd(&g_bar, 1u) + 1u;
        unsigned target = ((t + gridDim.x - 1u) / gridDim.x) * gridDim.x;
        while (*(volatile unsigned*)&g_bar < target) { }
        __threadfence();
    }
    __syncthreads();

    // phase 2: build S (reads via L2-coherent __ldcg)
    const int total  = n_typ * ROWV;
    const int stride = gridDim.x * blockDim.x;
    for (int i = blockIdx.x * blockDim.x + threadIdx.x; i < total; i += stride) {
        const int j  = i >> 5;
        const int ln = i & 31;
        int j1 = j + 1; if (j1 >= n_typ) j1 -= n_typ;
        int j2 = j + 2; if (j2 >= n_typ) j2 -= n_typ;
        int j3 = j + 3; if (j3 >= n_typ) j3 -= n_typ;
        const int t0 = __ldg(&lcom[j]);
        const int t1 = __ldg(&lcom[j1]);
        const int t2 = __ldg(&lcom[j2]);
        const int t3 = __ldg(&lcom[j3]);
        float4 v0 = __ldcg(&out4[t0 * ROWV + ln]);
        float4 v1 = __ldcg(&out4[t1 * ROWV + ln]);
        float4 v2 = __ldcg(&out4[t2 * ROWV + ln]);
        float4 v3 = __ldcg(&out4[t3 * ROWV + ln]);
        float4 s;
        s.x = (v0.x + v1.x) + (v2.x + v3.x);
        s.y = (v0.y + v1.y) + (v2.y + v3.y);
        s.z = (v0.z + v1.z) + (v2.z + v3.z);
        s.w = (v0.w + v1.w) + (v2.w + v3.w);
        g_S[i] = s;
    }
}

// ---------------------------------------------------------------------------
// sub3 (deg3==4): one warp per TWO entity rows, SPECULATIVE fast path.
// All loads issued in parallel: actual edges/rspec (for verification) PLUS
// speculative iv@base and S@affine-predicted-index. When edges arrive, a
// warp-uniform compare picks the speculative results (common case) or
// recomputes via the generic gather path (arbitrary edge lists -> correct).
// Critical path drops from edge->S serial (~810cy) to max(edge, iv) (~580cy).
// ---------------------------------------------------------------------------
__global__ __launch_bounds__(256)
void sub3_kernel(const float4* __restrict__ emb4,
                 const int4*   __restrict__ edges4,
                 const int*    __restrict__ lcom,
                 const int*    __restrict__ rspec,
                 float4*       __restrict__ out4,
                 int n_ent, int n_typ, float add, float inv_sum)
{
    const int warp = threadIdx.x >> 5;
    const int lane = threadIdx.x & 31;
    const int base = (blockIdx.x * (blockDim.x >> 5) + warp) * 2;
    if (base >= n_ent) return;
    const bool has1 = (base + 1) < n_ent;
    const int  n1   = has1 ? base + 1 : base;

    // affine params from the first two edge rows (L1/L2-hot broadcast)
    const int4 h0 = __ldg(&edges4[0]);
    const int4 h1 = __ldg(&edges4[1]);
    const int  b  = h0.x;
    int a = h1.x - b; if (a < 0) a += n_typ;

    // predicted S indices
    const int ex0 = (int)(((long long)a * base + b) % n_typ);
    int ex1 = ex0 + a; if (ex1 >= n_typ) ex1 -= n_typ;

    // ---- issue everything in parallel ----
    const int4 e0 = __ldg(&edges4[base]);          // actual edges (verify)
    const int4 e1 = __ldg(&edges4[n1]);
    const int  r0 = __ldg(&rspec[base]);           // actual targets (verify)
    const int  r1 = __ldg(&rspec[n1]);
    float4 iv0 = __ldcs(&emb4[base * ROWV + lane]);   // speculative
    float4 iv1 = __ldcs(&emb4[n1   * ROWV + lane]);   // speculative
    float4 a0  = __ldcg(&g_S[ex0 * ROWV + lane]);     // speculative
    float4 a1  = __ldcg(&g_S[ex1 * ROWV + lane]);     // speculative

    // ---- verify speculation (warp-uniform) ----
    int y0 = ex0 + 1; if (y0 >= n_typ) y0 -= n_typ;
    int z0 = ex0 + 2; if (z0 >= n_typ) z0 -= n_typ;
    int w0i = ex0 + 3; if (w0i >= n_typ) w0i -= n_typ;
    const bool ok0 = (e0.x == ex0) && (e0.y == y0) && (e0.z == z0)
                  && (e0.w == w0i) && (r0 == base);
    int y1 = ex1 + 1; if (y1 >= n_typ) y1 -= n_typ;
    int z1 = ex1 + 2; if (z1 >= n_typ) z1 -= n_typ;
    int w1i = ex1 + 3; if (w1i >= n_typ) w1i -= n_typ;
    const bool ok1 = (e1.x == ex1) && (e1.y == y1) && (e1.z == z1)
                  && (e1.w == w1i) && (r1 == n1);

    if (!ok0) {   // rare: generic recompute for entity 0
        const int t0 = __ldg(&lcom[e0.x]), t1 = __ldg(&lcom[e0.y]);
        const int t2 = __ldg(&lcom[e0.z]), t3 = __ldg(&lcom[e0.w]);
        float4 g0 = __ldcg(&out4[t0 * ROWV + lane]);
        float4 g1 = __ldcg(&out4[t1 * ROWV + lane]);
        float4 g2 = __ldcg(&out4[t2 * ROWV + lane]);
        float4 g3 = __ldcg(&out4[t3 * ROWV + lane]);
        a0.x = (g0.x + g1.x) + (g2.x + g3.x);
        a0.y = (g0.y + g1.y) + (g2.y + g3.y);
        a0.z = (g0.z + g1.z) + (g2.z + g3.z);
        a0.w = (g0.w + g1.w) + (g2.w + g3.w);
        iv0 = __ldcs(&emb4[r0 * ROWV + lane]);
    }
    if (!ok1) {   // rare: generic recompute for entity 1
        const int t0 = __ldg(&lcom[e1.x]), t1 = __ldg(&lcom[e1.y]);
        const int t2 = __ldg(&lcom[e1.z]), t3 = __ldg(&lcom[e1.w]);
        float4 g0 = __ldcg(&out4[t0 * ROWV + lane]);
        float4 g1 = __ldcg(&out4[t1 * ROWV + lane]);
        float4 g2 = __ldcg(&out4[t2 * ROWV + lane]);
        float4 g3 = __ldcg(&out4[t3 * ROWV + lane]);
        a1.x = (g0.x + g1.x) + (g2.x + g3.x);
        a1.y = (g0.y + g1.y) + (g2.y + g3.y);
        a1.z = (g0.z + g1.z) + (g2.z + g3.z);
        a1.w = (g0.w + g1.w) + (g2.w + g3.w);
        iv1 = __ldcs(&emb4[r1 * ROWV + lane]);
    }

    // ---- compute + streaming stores (store index = verified rspec) ----
    float4 o0;
    o0.x = iv0.x * (1.0f - (a0.x + add) * inv_sum);
    o0.y = iv0.y * (1.0f - (a0.y + add) * inv_sum);
    o0.z = iv0.z * (1.0f - (a0.z + add) * inv_sum);
    o0.w = iv0.w * (1.0f - (a0.w + add) * inv_sum);
    __stcs(&out4[r0 * ROWV + lane], o0);

    if (has1) {
        float4 o1;
        o1.x = iv1.x * (1.0f - (a1.x + add) * inv_sum);
        o1.y = iv1.y * (1.0f - (a1.y + add) * inv_sum);
        o1.z = iv1.z * (1.0f - (a1.z + add) * inv_sum);
        o1.w = iv1.w * (1.0f - (a1.w + add) * inv_sum);
        __stcs(&out4[r1 * ROWV + lane], o1);
    }
}

// ---------------------------------------------------------------------------
// Fallback kernels (generic shapes).
// ---------------------------------------------------------------------------
__global__ __launch_bounds__(512)
void sub2_kernel_gen(const float* __restrict__ emb,
                     const int*   __restrict__ s2row,
                     const int*   __restrict__ lspec,
                     const int*   __restrict__ rcom,
                     float*       __restrict__ out,
                     float addc, int deg2)
{
    __shared__ float part[4][DIM];
    const int c = blockIdx.x;
    const int d = threadIdx.x & (DIM - 1);
    const int g = threadIdx.x >> 7;
    const int* __restrict__ e = s2row + (size_t)c * deg2;
    const int chunk = deg2 >> 2;
    const int j0 = g * chunk;
    const int j1 = (g == 3) ? deg2 : j0 + chunk;
    float acc = 0.0f;
    #pragma unroll 8
    for (int j = j0; j < j1; ++j) {
        int src = __ldg(&lspec[__ldg(&e[j])]);
        acc += __ldcs(&emb[(size_t)src * DIM + d]);
    }
    part[g][d] = acc;
    __syncthreads();
    if (g == 0) {
        const int tgt = rcom[c];
        float v = __ldg(&emb[(size_t)tgt * DIM + d])
                + part[0][d] + part[1][d] + part[2][d] + part[3][d] + addc;
        out[(size_t)tgt * DIM + d] = v;
    }
}

__global__ __launch_bounds__(256)
void sub3_kernel_gen(const float* __restrict__ emb,
                     const int*   __restrict__ s3row,
                     const int*   __restrict__ lcom,
                     const int*   __restrict__ rspec,
                     float*       __restrict__ out,
                     int n_ent, float n_typ_f, int deg3)
{
    const int warp = threadIdx.x >> 5;
    const int lane = threadIdx.x & 31;
    const int n = blockIdx.x * (blockDim.x >> 5) + warp;
    if (n >= n_ent) return;

    const float4* __restrict__ out4 = (const float4*)out;
    const int* __restrict__ e = s3row + (size_t)n * deg3;

    float4 acc = make_float4(0.f, 0.f, 0.f, 0.f);
    for (int j = 0; j < deg3; ++j) {
        int t = __ldg(&lcom[__ldg(&e[j])]);
        float4 v = __ldg(&out4[(size_t)t * ROWV + lane]);
        acc.x += v.x; acc.y += v.y; acc.z += v.z; acc.w += v.w;
    }
    const float add     = n_typ_f - (float)deg3;
    const float inv_sum = 1.0f / (1.0f + (float)deg3);
    const int   tgt     = rspec[n];
    float4 iv = __ldcs(&((const float4*)emb)[(size_t)tgt * ROWV + lane]);
    float4 r;
    r.x = iv.x * (1.0f - (acc.x + add) * inv_sum);
    r.y = iv.y * (1.0f - (acc.y + add) * inv_sum);
    r.z = iv.z * (1.0f - (acc.z + add) * inv_sum);
    r.w = iv.w * (1.0f - (acc.w + add) * inv_sum);
    __stcs(&((float4*)out)[(size_t)tgt * ROWV + lane], r);
}

// ---------------------------------------------------------------------------
// Launch. Inputs (metadata order):
//  0 all_node_embedding f32 | 1 sub2_row | 2 sub2_col | 3 sub3_row | 4 sub3_col
//  5 left_specific | 6 right_common | 7 left_common | 8 right_specific
// ---------------------------------------------------------------------------
extern "C" void kernel_launch(void* const* d_in, const int* in_sizes, int n_in,
                              void* d_out, int out_size)
{
    const float* emb   = (const float*)d_in[0];
    const int*   s2row = (const int*)  d_in[1];
    const int*   s3row = (const int*)  d_in[3];
    const int*   lspec = (const int*)  d_in[5];
    const int*   rcom  = (const int*)  d_in[6];
    const int*   lcom  = (const int*)  d_in[7];
    const int*   rspec = (const int*)  d_in[8];
    float*       out   = (float*)d_out;

    const int n_ent = in_sizes[5];
    const int n_typ = in_sizes[6];
    const int deg2  = in_sizes[1] / n_typ;
    const int deg3  = in_sizes[3] / in_sizes[8];

    if (deg2 == 64 && deg3 == 4 && n_typ <= NTYP_MAX && n_ent >= 2) {
        // fused sub2 | barrier | build_S  (one launch, R10 form)
        sub2_buildS_fused<<<FUSED_GRID, 256>>>(
            (const float4*)emb, (const int4*)s2row, lspec, rcom, lcom,
            (float4*)out, (float)n_ent - (float)deg2, n_typ);

        // sub3: 2 entities per warp, speculative fast path
        const int warps_per_block = 8;
        const int ents_per_block  = warps_per_block * 2;
        const int blocks = (n_ent + ents_per_block - 1) / ents_per_block;
        sub3_kernel<<<blocks, warps_per_block * 32>>>(
            (const float4*)emb, (const int4*)s3row, lcom, rspec,
            (float4*)out, n_ent, n_typ,
            (float)n_typ - 4.0f, 1.0f / 5.0f);
    } else {
        // generic fallback path
        sub2_kernel_gen<<<n_typ, 512>>>(emb, s2row, lspec, rcom, out,
                                        (float)n_ent - (float)deg2, deg2);
        const int warps_per_block = 8;
        const int blocks = (n_ent + warps_per_block - 1) / warps_per_block;
        sub3_kernel_gen<<<blocks, warps_per_block * 32>>>(
            emb, s3row, lcom, rspec, out, n_ent, (float)n_typ, deg3);
    }
}